// round 4
// baseline (speedup 1.0000x reference)
#include <cuda_runtime.h>

// z = sum_{p,q,r} C[p*9+q*3+r] * u0_p * u1_q * u2_r,  u_i = (1, cos x_i, sin x_i)
__device__ float d_C[27];

// ---------------------------------------------------------------------------
// Kernel 1: build the 27 trilinear coefficients from q_weights (18 floats).
// ---------------------------------------------------------------------------
__global__ void build_coeffs(const float* __restrict__ qw) {
    __shared__ float Ure[8][8];
    __shared__ float Uim[8][8];
    __shared__ float A[8][8];

    int t = threadIdx.x;

    if (t < 8) {
        const int j = t;
        float sr[8], si[8];
        #pragma unroll
        for (int m = 0; m < 8; m++) { sr[m] = 0.f; si[m] = 0.f; }
        sr[j] = 1.0f;

        for (int l = 0; l < 3; l++) {
            #pragma unroll
            for (int q = 0; q < 3; q++) {
                float ty = qw[(l * 3 + q) * 2 + 0];
                float tz = qw[(l * 3 + q) * 2 + 1];
                int bit = 4 >> q;

                float c, s;
                __sincosf(0.5f * ty, &s, &c);
                #pragma unroll
                for (int m = 0; m < 8; m++) {
                    if (m & bit) continue;
                    int m1 = m | bit;
                    float ar = sr[m],  ai = si[m];
                    float br = sr[m1], bi = si[m1];
                    sr[m]  = c * ar - s * br;  si[m]  = c * ai - s * bi;
                    sr[m1] = s * ar + c * br;  si[m1] = s * ai + c * bi;
                }

                float cz, sz;
                __sincosf(0.5f * tz, &sz, &cz);
                #pragma unroll
                for (int m = 0; m < 8; m++) {
                    float ar = sr[m], ai = si[m];
                    if (m & bit) { sr[m] = cz * ar - sz * ai; si[m] = cz * ai + sz * ar; }
                    else         { sr[m] = cz * ar + sz * ai; si[m] = cz * ai - sz * ar; }
                }
            }
            #pragma unroll
            for (int m = 4; m < 6; m++) {           // CNOT01: swap (4,6),(5,7)
                int m1 = m | 2; float tmp;
                tmp = sr[m]; sr[m] = sr[m1]; sr[m1] = tmp;
                tmp = si[m]; si[m] = si[m1]; si[m1] = tmp;
            }
            #pragma unroll
            for (int m = 2; m < 8; m += 4) {        // CNOT12: swap (2,3),(6,7)
                int m1 = m | 1; float tmp;
                tmp = sr[m]; sr[m] = sr[m1]; sr[m1] = tmp;
                tmp = si[m]; si[m] = si[m1]; si[m1] = tmp;
            }
        }
        #pragma unroll
        for (int m = 0; m < 8; m++) { Ure[m][j] = sr[m]; Uim[m][j] = si[m]; }
    }
    __syncthreads();

    if (t < 64) {
        int j = t >> 3, k = t & 7;
        float a = 0.f;
        #pragma unroll
        for (int m = 0; m < 8; m++) {
            float sgn = (m & 4) ? -1.f : 1.f;
            a += sgn * (Ure[m][j] * Ure[m][k] + Uim[m][j] * Uim[m][k]);
        }
        A[j][k] = a;
    }
    __syncthreads();

    if (t < 27) {
        int p = t / 9, q = (t / 3) % 3, r = t % 3;
        float csum = 0.f;
        for (int j = 0; j < 8; j++) {
            for (int k = 0; k < 8; k++) {
                int a0 = (j >> 2) & 1, b0 = (k >> 2) & 1;
                int a1 = (j >> 1) & 1, b1 = (k >> 1) & 1;
                int a2 = j & 1,        b2 = k & 1;
                float g0 = (a0 == b0) ? ((p == 0) ? 0.5f : (p == 1) ? (a0 ? -0.5f : 0.5f) : 0.f)
                                      : ((p == 2) ? 0.5f : 0.f);
                float g1 = (a1 == b1) ? ((q == 0) ? 0.5f : (q == 1) ? (a1 ? -0.5f : 0.5f) : 0.f)
                                      : ((q == 2) ? 0.5f : 0.f);
                float g2 = (a2 == b2) ? ((r == 0) ? 0.5f : (r == 1) ? (a2 ? -0.5f : 0.5f) : 0.f)
                                      : ((r == 2) ? 0.5f : 0.f);
                csum += A[j][k] * g0 * g1 * g2;
            }
        }
        d_C[t] = csum;
    }
}

// ---------------------------------------------------------------------------
// Kernel 2: evaluate. SPT=2 (distinct SB slots per load), fine-grained grid
// (2048 blocks), forced 6 blocks/SM for occupancy, block-contiguous tiles.
// ---------------------------------------------------------------------------
static constexpr int SPT = 2;
static constexpr int BLOCK = 256;

__global__ void __launch_bounds__(BLOCK, 6) vqc_eval(const float4* __restrict__ in,
                                                     float* __restrict__ out, int B) {
    __shared__ float cs[27];
    if (threadIdx.x < 27) cs[threadIdx.x] = d_C[threadIdx.x];

    // Block-contiguous: block b covers rows [b*512, b*512+512)
    const int base = blockIdx.x * (BLOCK * SPT) + threadIdx.x;

    int i0 = base;
    int i1 = base + BLOCK;
    int c0 = (i0 < B) ? i0 : (B - 1);
    int c1 = (i1 < B) ? i1 : (B - 1);
    float4 x0 = in[(size_t)c0 * 2];   // first 16B of each 32B row
    float4 x1 = in[(size_t)c1 * 2];

    __syncthreads();   // cs ready (arrives under the loads)

    float z[SPT];
    float4 xs[SPT] = {x0, x1};
    #pragma unroll
    for (int k = 0; k < SPT; k++) {
        float C0, S0, C1, S1, C2, S2;
        __sincosf(xs[k].x, &S0, &C0);
        __sincosf(xs[k].y, &S1, &C1);
        __sincosf(xs[k].z, &S2, &C2);

        float u0[3] = {1.f, C0, S0};
        float u1[3] = {1.f, C1, S1};
        float acc = 0.f;
        #pragma unroll
        for (int p = 0; p < 3; p++) {
            #pragma unroll
            for (int q = 0; q < 3; q++) {
                const float* c3 = &cs[p * 9 + q * 3];
                float w = c3[0];
                w = fmaf(c3[1], C2, w);
                w = fmaf(c3[2], S2, w);
                acc = fmaf(u0[p] * u1[q], w, acc);
            }
        }
        z[k] = acc;
    }

    if (i0 < B) out[i0] = z[0];
    if (i1 < B) out[i1] = z[1];
}

extern "C" void kernel_launch(void* const* d_in, const int* in_sizes, int n_in,
                              void* d_out, int out_size) {
    const float* inputs = (const float*)d_in[0];   // (B, 8) float32
    const float* qw     = (const float*)d_in[1];   // (3, 3, 2) float32
    float* out          = (float*)d_out;           // (B, 1) float32

    int B = in_sizes[0] / 8;

    build_coeffs<<<1, 64>>>(qw);

    int grid = (B + BLOCK * SPT - 1) / (BLOCK * SPT);   // 2048 for B = 2^20
    vqc_eval<<<grid, BLOCK>>>((const float4*)inputs, out, B);
}

// round 5
// speedup vs baseline: 1.1830x; 1.1830x over previous
#include <cuda_runtime.h>

// z = sum_{p,q,r} C[p*9+q*3+r] * u0_p * u1_q * u2_r,  u_i = (1, cos x_i, sin x_i)
__device__ float d_C[27];

// ---------------------------------------------------------------------------
// Kernel 1: build the 27 trilinear coefficients from q_weights (18 floats).
// ---------------------------------------------------------------------------
__global__ void build_coeffs(const float* __restrict__ qw) {
    __shared__ float Ure[8][8];
    __shared__ float Uim[8][8];
    __shared__ float A[8][8];

    int t = threadIdx.x;

    if (t < 8) {
        const int j = t;
        float sr[8], si[8];
        #pragma unroll
        for (int m = 0; m < 8; m++) { sr[m] = 0.f; si[m] = 0.f; }
        sr[j] = 1.0f;

        for (int l = 0; l < 3; l++) {
            #pragma unroll
            for (int q = 0; q < 3; q++) {
                float ty = qw[(l * 3 + q) * 2 + 0];
                float tz = qw[(l * 3 + q) * 2 + 1];
                int bit = 4 >> q;

                float c, s;
                __sincosf(0.5f * ty, &s, &c);
                #pragma unroll
                for (int m = 0; m < 8; m++) {
                    if (m & bit) continue;
                    int m1 = m | bit;
                    float ar = sr[m],  ai = si[m];
                    float br = sr[m1], bi = si[m1];
                    sr[m]  = c * ar - s * br;  si[m]  = c * ai - s * bi;
                    sr[m1] = s * ar + c * br;  si[m1] = s * ai + c * bi;
                }

                float cz, sz;
                __sincosf(0.5f * tz, &sz, &cz);
                #pragma unroll
                for (int m = 0; m < 8; m++) {
                    float ar = sr[m], ai = si[m];
                    if (m & bit) { sr[m] = cz * ar - sz * ai; si[m] = cz * ai + sz * ar; }
                    else         { sr[m] = cz * ar + sz * ai; si[m] = cz * ai - sz * ar; }
                }
            }
            #pragma unroll
            for (int m = 4; m < 6; m++) {           // CNOT01: swap (4,6),(5,7)
                int m1 = m | 2; float tmp;
                tmp = sr[m]; sr[m] = sr[m1]; sr[m1] = tmp;
                tmp = si[m]; si[m] = si[m1]; si[m1] = tmp;
            }
            #pragma unroll
            for (int m = 2; m < 8; m += 4) {        // CNOT12: swap (2,3),(6,7)
                int m1 = m | 1; float tmp;
                tmp = sr[m]; sr[m] = sr[m1]; sr[m1] = tmp;
                tmp = si[m]; si[m] = si[m1]; si[m1] = tmp;
            }
        }
        #pragma unroll
        for (int m = 0; m < 8; m++) { Ure[m][j] = sr[m]; Uim[m][j] = si[m]; }
    }
    __syncthreads();

    if (t < 64) {
        int j = t >> 3, k = t & 7;
        float a = 0.f;
        #pragma unroll
        for (int m = 0; m < 8; m++) {
            float sgn = (m & 4) ? -1.f : 1.f;
            a += sgn * (Ure[m][j] * Ure[m][k] + Uim[m][j] * Uim[m][k]);
        }
        A[j][k] = a;
    }
    __syncthreads();

    if (t < 27) {
        int p = t / 9, q = (t / 3) % 3, r = t % 3;
        float csum = 0.f;
        for (int j = 0; j < 8; j++) {
            for (int k = 0; k < 8; k++) {
                int a0 = (j >> 2) & 1, b0 = (k >> 2) & 1;
                int a1 = (j >> 1) & 1, b1 = (k >> 1) & 1;
                int a2 = j & 1,        b2 = k & 1;
                float g0 = (a0 == b0) ? ((p == 0) ? 0.5f : (p == 1) ? (a0 ? -0.5f : 0.5f) : 0.f)
                                      : ((p == 2) ? 0.5f : 0.f);
                float g1 = (a1 == b1) ? ((q == 0) ? 0.5f : (q == 1) ? (a1 ? -0.5f : 0.5f) : 0.f)
                                      : ((q == 2) ? 0.5f : 0.f);
                float g2 = (a2 == b2) ? ((r == 0) ? 0.5f : (r == 1) ? (a2 ? -0.5f : 0.5f) : 0.f)
                                      : ((r == 2) ? 0.5f : 0.f);
                csum += A[j][k] * g0 * g1 * g2;
            }
        }
        d_C[t] = csum;
    }
}

// ---------------------------------------------------------------------------
// FMA-only sincos: no MUFU. Range-reduce by pi (k = rint(x/pi)), degree-9
// sin / degree-10 cos polynomials on [-pi/2, pi/2], parity sign via XOR.
// Abs error < ~5e-6 for |x| <= ~30 — far inside the 1e-3 gate.
// ---------------------------------------------------------------------------
__device__ __forceinline__ void fma_sincos(float x, float& so, float& co) {
    const float INV_PI = 0.3183098861837907f;
    const float PI_HI  = 3.14159274101257324f;   // float(pi)
    const float PI_LO  = -8.74227765734759e-8f;  // pi - float(pi)

    float k = rintf(x * INV_PI);
    float y = fmaf(-k, PI_HI, x);
    y = fmaf(-k, PI_LO, y);
    unsigned flip = ((unsigned)((int)k & 1)) << 31;   // (-1)^k as sign bit

    float s2 = y * y;

    // sin(y) = y + y*s2*(P1 + s2*(P2 + s2*(P3 + s2*P4)))
    float sp = fmaf(s2, 2.7557314e-6f, -1.9841271e-4f);
    sp = fmaf(s2, sp, 8.3333310e-3f);
    sp = fmaf(s2, sp, -1.6666667e-1f);
    float siny = fmaf(y * s2, sp, y);

    // cos(y) = 1 + s2*(Q1 + s2*(Q2 + s2*(Q3 + s2*(Q4 + s2*Q5))))
    float cp = fmaf(s2, -2.7557319e-7f, 2.4801587e-5f);
    cp = fmaf(s2, cp, -1.3888889e-3f);
    cp = fmaf(s2, cp, 4.1666668e-2f);
    cp = fmaf(s2, cp, -5.0e-1f);
    float cosy = fmaf(s2, cp, 1.0f);

    so = __int_as_float(__float_as_int(siny) ^ flip);
    co = __int_as_float(__float_as_int(cosy) ^ flip);
}

// ---------------------------------------------------------------------------
// Kernel 2: evaluate. SPT=4 front-batched loads (best geometry from R1),
// zero MUFU in the hot path.
// ---------------------------------------------------------------------------
static constexpr int SPT = 4;
static constexpr int BLOCK = 256;

__global__ void __launch_bounds__(BLOCK) vqc_eval(const float4* __restrict__ in,
                                                  float* __restrict__ out, int B) {
    __shared__ float cs[27];
    if (threadIdx.x < 27) cs[threadIdx.x] = d_C[threadIdx.x];

    const int T = gridDim.x * BLOCK;
    const int t = blockIdx.x * BLOCK + threadIdx.x;

    float4 x[SPT];
    #pragma unroll
    for (int k = 0; k < SPT; k++) {
        int i = t + k * T;
        i = (i < B) ? i : (B - 1);
        x[k] = in[(size_t)i * 2];     // first 16B of the 32B row
    }
    __syncthreads();

    #pragma unroll
    for (int k = 0; k < SPT; k++) {
        float C0, S0, C1, S1, C2, S2;
        fma_sincos(x[k].x, S0, C0);
        fma_sincos(x[k].y, S1, C1);
        fma_sincos(x[k].z, S2, C2);

        float u0[3] = {1.f, C0, S0};
        float u1[3] = {1.f, C1, S1};
        float z = 0.f;
        #pragma unroll
        for (int p = 0; p < 3; p++) {
            #pragma unroll
            for (int q = 0; q < 3; q++) {
                const float* c3 = &cs[p * 9 + q * 3];
                float w = c3[0];
                w = fmaf(c3[1], C2, w);
                w = fmaf(c3[2], S2, w);
                z = fmaf(u0[p] * u1[q], w, z);
            }
        }
        int i = t + k * T;
        if (i < B) out[i] = z;
    }
}

extern "C" void kernel_launch(void* const* d_in, const int* in_sizes, int n_in,
                              void* d_out, int out_size) {
    const float* inputs = (const float*)d_in[0];   // (B, 8) float32
    const float* qw     = (const float*)d_in[1];   // (3, 3, 2) float32
    float* out          = (float*)d_out;           // (B, 1) float32

    int B = in_sizes[0] / 8;

    build_coeffs<<<1, 64>>>(qw);

    int grid = (B + BLOCK * SPT - 1) / (BLOCK * SPT);   // 1024 for B = 2^20
    vqc_eval<<<grid, BLOCK>>>((const float4*)inputs, out, B);
}